// round 6
// baseline (speedup 1.0000x reference)
#include <cuda_runtime.h>
#include <math.h>

typedef unsigned int u32;

#define NN 10000
#define EE 160000
#define DD 512
#define ND (NN * DD)          /* 5,120,000 */
#define MPAD 10112            /* 79 * 128 */

// ---------------- scratch (static device globals: allocation-free) ----------
__device__ float g_xs[ND];          // dropout'd + src-normalized features
__device__ float g_tmp[ND];         // layer output
__device__ float g_agg[MPAD * DD];  // scatter target (padded rows zeroed)
__device__ float g_ido[NN];         // deg_out^-0.5
__device__ float g_idi[NN];         // deg_in^-0.5
__device__ int   g_dego[NN];
__device__ int   g_degi[NN];

// ---------------- JAX-compatible threefry2x32 -------------------------------
struct U2 { u32 a, b; };

constexpr u32 rotl_c(u32 v, int r) { return (v << r) | (v >> (32 - r)); }

constexpr U2 tf_host(u32 k0, u32 k1, u32 x0, u32 x1) {
    u32 ks2 = 0x1BD11BDAu ^ k0 ^ k1;
    x0 += k0; x1 += k1;
    const int R0[4] = {13, 15, 26, 6};
    const int R1[4] = {17, 29, 16, 24};
    for (int g = 0; g < 5; ++g) {
        for (int i = 0; i < 4; ++i) {
            int r = (g & 1) ? R1[i] : R0[i];
            x0 += x1; x1 = rotl_c(x1, r); x1 ^= x0;
        }
        switch (g) {
            case 0: x0 += k1;  x1 += ks2 + 1u; break;
            case 1: x0 += ks2; x1 += k0  + 2u; break;
            case 2: x0 += k0;  x1 += k1  + 3u; break;
            case 3: x0 += k1;  x1 += ks2 + 4u; break;
            default: x0 += ks2; x1 += k0 + 5u; break;
        }
    }
    return U2{x0, x1};
}

// PARTITIONABLE threefry (modern JAX default):
//   split(key(42), 3) -> dk[i] = threefry2x32((0,42), (0, i))   (fold-like split)
constexpr U2 DK0 = tf_host(0u, 42u, 0u, 0u);
constexpr U2 DK1 = tf_host(0u, 42u, 0u, 1u);
constexpr U2 DK2 = tf_host(0u, 42u, 0u, 2u);

__device__ __forceinline__ void tf_dev(u32 k0, u32 k1, u32& x0, u32& x1) {
    u32 ks2 = 0x1BD11BDAu ^ k0 ^ k1;
    x0 += k0; x1 += k1;
#define TFR(r) { x0 += x1; x1 = (x1 << (r)) | (x1 >> (32 - (r))); x1 ^= x0; }
    TFR(13) TFR(15) TFR(26) TFR(6)   x0 += k1;  x1 += ks2 + 1u;
    TFR(17) TFR(29) TFR(16) TFR(24)  x0 += ks2; x1 += k0  + 2u;
    TFR(13) TFR(15) TFR(26) TFR(6)   x0 += k0;  x1 += k1  + 3u;
    TFR(17) TFR(29) TFR(16) TFR(24)  x0 += k1;  x1 += ks2 + 4u;
    TFR(13) TFR(15) TFR(26) TFR(6)   x0 += ks2; x1 += k0  + 5u;
#undef TFR
}

// ---------------- degree kernels --------------------------------------------
__global__ void k_zero_deg() {
    int i = blockIdx.x * blockDim.x + threadIdx.x;
    if (i < NN) { g_dego[i] = 0; g_degi[i] = 0; }
}

__global__ void k_count_deg(const int* __restrict__ src, const int* __restrict__ dst) {
    int e = blockIdx.x * blockDim.x + threadIdx.x;
    if (e < EE) {
        atomicAdd(&g_dego[src[e]], 1);
        atomicAdd(&g_degi[dst[e]], 1);
    }
}

__global__ void k_inv_deg() {
    int i = blockIdx.x * blockDim.x + threadIdx.x;
    if (i < NN) {
        g_ido[i] = rsqrtf(fmaxf((float)g_dego[i], 1.0f));
        g_idi[i] = rsqrtf(fmaxf((float)g_degi[i], 1.0f));
    }
}

// ---------------- fused dropout + src-degree normalization ------------------
// Partitionable random_bits: element j uses counter (hi=0, lo=j);
// 32-bit word = out0 ^ out1. uniform = bitcast((bits>>9)|0x3f800000)-1; keep = u<0.8.
__global__ void k_dropout_scale(const float* __restrict__ xin_arg, u32 k0, u32 k1) {
    const float* __restrict__ xin = xin_arg ? xin_arg : (const float*)g_tmp;
    int q = blockIdx.x * blockDim.x + threadIdx.x;   // quad index
    if (q >= ND / 4) return;
    int j0 = q << 2;
    float4 v = *(const float4*)(xin + j0);
    float s = g_ido[j0 >> 9] * 1.25f;    // same row for all 4 lanes (512 % 4 == 0)
    float vv[4] = {v.x, v.y, v.z, v.w};
    float o[4];
#pragma unroll
    for (int t = 0; t < 4; ++t) {
        u32 x0 = 0u, x1 = (u32)(j0 + t);
        tf_dev(k0, k1, x0, x1);
        u32 bits = x0 ^ x1;
        float u = __uint_as_float((bits >> 9) | 0x3f800000u) - 1.0f;
        o[t] = (u < 0.8f) ? vv[t] * s : 0.0f;
    }
    *(float4*)(g_xs + j0) = make_float4(o[0], o[1], o[2], o[3]);
}

// ---------------- zero the aggregation buffer -------------------------------
__global__ void k_zero_agg() {
    int i = blockIdx.x * blockDim.x + threadIdx.x;
    if (i < (MPAD * DD) / 4) {
        ((float4*)g_agg)[i] = make_float4(0.f, 0.f, 0.f, 0.f);
    }
}

// ---------------- edge scatter: agg[dst] += xs[src] * ew --------------------
// 128 threads per edge, float4 per thread, vectorized L2 reduction.
__global__ void k_scatter(const int* __restrict__ src, const int* __restrict__ dst,
                          const float* __restrict__ ew) {
    int idx = blockIdx.x * blockDim.x + threadIdx.x;   // < EE * 128 = 20.48M
    if (idx >= EE * 128) return;
    int e = idx >> 7;
    int c = (idx & 127) << 2;
    int s = src[e];
    int d = dst[e];
    float w = ew[e];
    float4 v = *(const float4*)(g_xs + (size_t)s * DD + c);
    float* p = g_agg + (size_t)d * DD + c;
    asm volatile("red.global.add.v4.f32 [%0], {%1, %2, %3, %4};"
                 :: "l"(p), "f"(v.x * w), "f"(v.y * w), "f"(v.z * w), "f"(v.w * w)
                 : "memory");
}

// ---------------- GEMM: C = (g_agg @ B) * deg_in^-0.5 + bias (+ELU) --------
// M=10000 (padded 10112), N=512, K=512. Tile 128x64, 256 threads, 8x4 microtile.
template<bool DO_ELU>
__global__ __launch_bounds__(256)
void k_gemm(const float* __restrict__ B, const float* __restrict__ bias,
            float* __restrict__ Carg) {
    float* __restrict__ C = Carg ? Carg : (float*)g_tmp;
    __shared__ float As[8][128];
    __shared__ float Bs[8][64];

    const int bm = blockIdx.x * 128;
    const int bn = blockIdx.y * 64;
    const int t  = threadIdx.x;
    const int tx = t & 15;          // N direction (16 -> 4 cols each)
    const int ty = t >> 4;          // M direction (16 -> 8 rows each)

    const int a_row  = t >> 1;          // 0..127
    const int a_half = (t & 1) << 2;    // 0 or 4
    const float* Ap = g_agg + (size_t)(bm + a_row) * DD + a_half;
    const float* Bp = B + (size_t)(t >> 4) * DD + bn + ((t & 15) << 2); // valid for t<128

    float acc[8][4];
#pragma unroll
    for (int i = 0; i < 8; ++i)
#pragma unroll
        for (int j = 0; j < 4; ++j) acc[i][j] = 0.0f;

    for (int k0 = 0; k0 < DD; k0 += 8) {
        float4 av = *(const float4*)(Ap + k0);
        float4 bv = make_float4(0.f, 0.f, 0.f, 0.f);
        if (t < 128) bv = *(const float4*)(Bp + (size_t)k0 * DD);

        __syncthreads();   // previous tile fully consumed
        As[a_half + 0][a_row] = av.x;
        As[a_half + 1][a_row] = av.y;
        As[a_half + 2][a_row] = av.z;
        As[a_half + 3][a_row] = av.w;
        if (t < 128) *(float4*)&Bs[t >> 4][(t & 15) << 2] = bv;
        __syncthreads();

#pragma unroll
        for (int kk = 0; kk < 8; ++kk) {
            float4 a0 = *(const float4*)&As[kk][(ty << 3)];
            float4 a1 = *(const float4*)&As[kk][(ty << 3) + 4];
            float4 bb = *(const float4*)&Bs[kk][(tx << 2)];
            float a[8] = {a0.x, a0.y, a0.z, a0.w, a1.x, a1.y, a1.z, a1.w};
            float b4[4] = {bb.x, bb.y, bb.z, bb.w};
#pragma unroll
            for (int i = 0; i < 8; ++i)
#pragma unroll
                for (int j = 0; j < 4; ++j)
                    acc[i][j] += a[i] * b4[j];
        }
    }

    const int col = bn + (tx << 2);
    float bb0 = bias[col + 0], bb1 = bias[col + 1], bb2 = bias[col + 2], bb3 = bias[col + 3];
#pragma unroll
    for (int i = 0; i < 8; ++i) {
        int row = bm + (ty << 3) + i;
        if (row < NN) {
            float s = g_idi[row];
            float4 o;
            o.x = acc[i][0] * s + bb0;
            o.y = acc[i][1] * s + bb1;
            o.z = acc[i][2] * s + bb2;
            o.w = acc[i][3] * s + bb3;
            if (DO_ELU) {
                o.x = o.x > 0.f ? o.x : expm1f(o.x);
                o.y = o.y > 0.f ? o.y : expm1f(o.y);
                o.z = o.z > 0.f ? o.z : expm1f(o.z);
                o.w = o.w > 0.f ? o.w : expm1f(o.w);
            }
            *(float4*)&C[(size_t)row * DD + col] = o;
        }
    }
}

// ---------------- launch ----------------------------------------------------
extern "C" void kernel_launch(void* const* d_in, const int* in_sizes, int n_in,
                              void* d_out, int out_size) {
    (void)in_sizes; (void)n_in; (void)out_size;
    const float* h   = (const float*)d_in[0];
    const int*   src = (const int*)  d_in[1];
    const int*   dst = (const int*)  d_in[2];
    const float* ew  = (const float*)d_in[3];
    const float* W0  = (const float*)d_in[4];
    const float* b0  = (const float*)d_in[5];
    const float* W1  = (const float*)d_in[6];
    const float* b1  = (const float*)d_in[7];
    const float* W2  = (const float*)d_in[8];
    const float* b2  = (const float*)d_in[9];
    float* out = (float*)d_out;

    const int TB = 256;
    dim3 gemm_grid(MPAD / 128, DD / 64);                 // 79 x 8
    const int drop_blocks  = (ND / 4 + TB - 1) / TB;     // 5000
    const int scat_blocks  = (EE * 128) / TB;            // 80000
    const int zero_blocks  = ((MPAD * DD) / 4 + TB - 1) / TB;

    // degrees (recomputed each call: deterministic, cheap)
    k_zero_deg<<<(NN + TB - 1) / TB, TB>>>();
    k_count_deg<<<(EE + TB - 1) / TB, TB>>>(src, dst);
    k_inv_deg<<<(NN + TB - 1) / TB, TB>>>();

    // layer 0
    k_dropout_scale<<<drop_blocks, TB>>>(h, DK0.a, DK0.b);
    k_zero_agg<<<zero_blocks, TB>>>();
    k_scatter<<<scat_blocks, TB>>>(src, dst, ew);
    k_gemm<true><<<gemm_grid, TB>>>(W0, b0, nullptr);

    // layer 1
    k_dropout_scale<<<drop_blocks, TB>>>(nullptr, DK1.a, DK1.b);
    k_zero_agg<<<zero_blocks, TB>>>();
    k_scatter<<<scat_blocks, TB>>>(src, dst, ew);
    k_gemm<true><<<gemm_grid, TB>>>(W1, b1, nullptr);

    // layer 2 (no activation, write to d_out)
    k_dropout_scale<<<drop_blocks, TB>>>(nullptr, DK2.a, DK2.b);
    k_zero_agg<<<zero_blocks, TB>>>();
    k_scatter<<<scat_blocks, TB>>>(src, dst, ew);
    k_gemm<false><<<gemm_grid, TB>>>(W2, b2, out);
}

// round 7
// speedup vs baseline: 1.2215x; 1.2215x over previous
#include <cuda_runtime.h>
#include <math.h>

typedef unsigned int u32;

#define NN 10000
#define EE 160000
#define DD 512
#define ND (NN * DD)          /* 5,120,000 */
#define MPAD 10112            /* 79 * 128 */

// ---------------- scratch (static device globals: allocation-free) ----------
__device__ float g_xs[ND];            // dropout'd + src-normalized features
__device__ float g_tmp[ND];           // layer output
__device__ float g_agg[MPAD * DD];    // aggregation target (padded rows stay 0)
__device__ float g_ido[NN];           // deg_out^-0.5
__device__ float g_idi[NN];           // deg_in^-0.5
__device__ int   g_dego[NN];
__device__ int   g_degi[NN];
__device__ int   g_roff[NN + 1];      // CSR row offsets (by dst)
__device__ int   g_cur[NN];           // fill cursors
__device__ int   g_esrc[EE];          // src per CSR slot
__device__ float g_eew[EE];           // edge weight per CSR slot

// ---------------- JAX-compatible threefry2x32 (partitionable) ---------------
struct U2 { u32 a, b; };

constexpr u32 rotl_c(u32 v, int r) { return (v << r) | (v >> (32 - r)); }

constexpr U2 tf_host(u32 k0, u32 k1, u32 x0, u32 x1) {
    u32 ks2 = 0x1BD11BDAu ^ k0 ^ k1;
    x0 += k0; x1 += k1;
    const int R0[4] = {13, 15, 26, 6};
    const int R1[4] = {17, 29, 16, 24};
    for (int g = 0; g < 5; ++g) {
        for (int i = 0; i < 4; ++i) {
            int r = (g & 1) ? R1[i] : R0[i];
            x0 += x1; x1 = rotl_c(x1, r); x1 ^= x0;
        }
        switch (g) {
            case 0: x0 += k1;  x1 += ks2 + 1u; break;
            case 1: x0 += ks2; x1 += k0  + 2u; break;
            case 2: x0 += k0;  x1 += k1  + 3u; break;
            case 3: x0 += k1;  x1 += ks2 + 4u; break;
            default: x0 += ks2; x1 += k0 + 5u; break;
        }
    }
    return U2{x0, x1};
}

// split(key(42), 3) -> dk[i] = threefry2x32((0,42), (0, i))
constexpr U2 DK0 = tf_host(0u, 42u, 0u, 0u);
constexpr U2 DK1 = tf_host(0u, 42u, 0u, 1u);
constexpr U2 DK2 = tf_host(0u, 42u, 0u, 2u);

__device__ __forceinline__ void tf_dev(u32 k0, u32 k1, u32& x0, u32& x1) {
    u32 ks2 = 0x1BD11BDAu ^ k0 ^ k1;
    x0 += k0; x1 += k1;
#define TFR(r) { x0 += x1; x1 = (x1 << (r)) | (x1 >> (32 - (r))); x1 ^= x0; }
    TFR(13) TFR(15) TFR(26) TFR(6)   x0 += k1;  x1 += ks2 + 1u;
    TFR(17) TFR(29) TFR(16) TFR(24)  x0 += ks2; x1 += k0  + 2u;
    TFR(13) TFR(15) TFR(26) TFR(6)   x0 += k0;  x1 += k1  + 3u;
    TFR(17) TFR(29) TFR(16) TFR(24)  x0 += k1;  x1 += ks2 + 4u;
    TFR(13) TFR(15) TFR(26) TFR(6)   x0 += ks2; x1 += k0  + 5u;
#undef TFR
}

// ---------------- degree + CSR build ---------------------------------------
__global__ void k_zero_deg() {
    int i = blockIdx.x * blockDim.x + threadIdx.x;
    if (i < NN) { g_dego[i] = 0; g_degi[i] = 0; }
}

__global__ void k_count_deg(const int* __restrict__ src, const int* __restrict__ dst) {
    int e = blockIdx.x * blockDim.x + threadIdx.x;
    if (e < EE) {
        atomicAdd(&g_dego[src[e]], 1);
        atomicAdd(&g_degi[dst[e]], 1);
    }
}

__global__ void k_inv_deg() {
    int i = blockIdx.x * blockDim.x + threadIdx.x;
    if (i < NN) {
        g_ido[i] = rsqrtf(fmaxf((float)g_dego[i], 1.0f));
        g_idi[i] = rsqrtf(fmaxf((float)g_degi[i], 1.0f));
    }
}

// exclusive prefix sum of g_degi -> g_roff / g_cur. One block of 1024 threads.
__global__ void k_scan() {
    __shared__ int s[1024];
    const int t = threadIdx.x;
    const int PER = 10;                     // 1024*10 >= NN
    const int base = t * PER;
    int loc[PER];
    int sum = 0;
#pragma unroll
    for (int i = 0; i < PER; ++i) {
        loc[i] = sum;
        int idx = base + i;
        sum += (idx < NN) ? g_degi[idx] : 0;
    }
    s[t] = sum;
    __syncthreads();
    for (int off = 1; off < 1024; off <<= 1) {
        int v = (t >= off) ? s[t - off] : 0;
        __syncthreads();
        s[t] += v;
        __syncthreads();
    }
    int excl = (t > 0) ? s[t - 1] : 0;
#pragma unroll
    for (int i = 0; i < PER; ++i) {
        int idx = base + i;
        if (idx < NN) {
            int o = excl + loc[i];
            g_roff[idx] = o;
            g_cur[idx] = o;
        }
    }
    if (t == 1023) g_roff[NN] = s[1023];
}

__global__ void k_fill(const int* __restrict__ src, const int* __restrict__ dst,
                       const float* __restrict__ ew) {
    int e = blockIdx.x * blockDim.x + threadIdx.x;
    if (e < EE) {
        int pos = atomicAdd(&g_cur[dst[e]], 1);
        g_esrc[pos] = src[e];
        g_eew[pos] = ew[e];
    }
}

// ---------------- fused dropout + src-degree normalization ------------------
__global__ void k_dropout_scale(const float* __restrict__ xin_arg, u32 k0, u32 k1) {
    const float* __restrict__ xin = xin_arg ? xin_arg : (const float*)g_tmp;
    int q = blockIdx.x * blockDim.x + threadIdx.x;   // quad index
    if (q >= ND / 4) return;
    int j0 = q << 2;
    float4 v = *(const float4*)(xin + j0);
    float s = g_ido[j0 >> 9] * 1.25f;    // same row for all 4 lanes
    float vv[4] = {v.x, v.y, v.z, v.w};
    float o[4];
#pragma unroll
    for (int t = 0; t < 4; ++t) {
        u32 x0 = 0u, x1 = (u32)(j0 + t);
        tf_dev(k0, k1, x0, x1);
        u32 bits = x0 ^ x1;
        float u = __uint_as_float((bits >> 9) | 0x3f800000u) - 1.0f;
        o[t] = (u < 0.8f) ? vv[t] * s : 0.0f;
    }
    *(float4*)(g_xs + j0) = make_float4(o[0], o[1], o[2], o[3]);
}

// ---------------- CSR aggregation: agg[n] = sum_in xs[src]*w ---------------
// One block (128 threads) per destination node; register accumulation, no atomics.
__global__ __launch_bounds__(128)
void k_aggregate() {
    const int n = blockIdx.x;
    const int c = threadIdx.x << 2;       // column (float4)
    const int beg = g_roff[n];
    const int end = g_roff[n + 1];
    float4 acc = make_float4(0.f, 0.f, 0.f, 0.f);
    int i = beg;
    for (; i + 1 < end; i += 2) {
        int s0 = g_esrc[i],     s1 = g_esrc[i + 1];
        float w0 = g_eew[i],    w1 = g_eew[i + 1];
        float4 v0 = *(const float4*)(g_xs + (size_t)s0 * DD + c);
        float4 v1 = *(const float4*)(g_xs + (size_t)s1 * DD + c);
        acc.x += v0.x * w0 + v1.x * w1;
        acc.y += v0.y * w0 + v1.y * w1;
        acc.z += v0.z * w0 + v1.z * w1;
        acc.w += v0.w * w0 + v1.w * w1;
    }
    if (i < end) {
        int s0 = g_esrc[i];
        float w0 = g_eew[i];
        float4 v0 = *(const float4*)(g_xs + (size_t)s0 * DD + c);
        acc.x += v0.x * w0; acc.y += v0.y * w0;
        acc.z += v0.z * w0; acc.w += v0.w * w0;
    }
    *(float4*)(g_agg + (size_t)n * DD + c) = acc;
}

// ---------------- GEMM: C = (g_agg @ B) * deg_in^-0.5 + bias (+ELU) --------
// 128x128x8 tiles, 256 threads, 8x8 microtile, double-buffered SMEM.
template<bool DO_ELU>
__global__ __launch_bounds__(256, 2)
void k_gemm(const float* __restrict__ B, const float* __restrict__ bias,
            float* __restrict__ Carg) {
    float* __restrict__ C = Carg ? Carg : (float*)g_tmp;
    __shared__ float As[2][8][132];
    __shared__ float Bs[2][8][132];

    const int bm = blockIdx.x * 128;
    const int bn = blockIdx.y * 128;
    const int t  = threadIdx.x;
    const int tx = t & 15;            // N quad index
    const int ty = t >> 4;            // M quad index

    // global-load assignments
    const int ar = t >> 1;            // A row 0..127
    const int ak = (t & 1) << 2;      // A k offset {0,4}
    const int br = t >> 5;            // B k row 0..7
    const int bc = (t & 31) << 2;     // B col 0..124

    const float* Ap = g_agg + (size_t)(bm + ar) * DD + ak;
    const float* Bp = B + (size_t)br * DD + bn + bc;

    float acc[8][8];
#pragma unroll
    for (int i = 0; i < 8; ++i)
#pragma unroll
        for (int j = 0; j < 8; ++j) acc[i][j] = 0.0f;

    float4 aN = *(const float4*)(Ap);
    float4 bN = *(const float4*)(Bp);
    int buf = 0;
    As[0][ak + 0][ar] = aN.x;
    As[0][ak + 1][ar] = aN.y;
    As[0][ak + 2][ar] = aN.z;
    As[0][ak + 3][ar] = aN.w;
    *(float4*)&Bs[0][br][bc] = bN;
    __syncthreads();

    const int NKT = DD / 8;           // 64
    for (int kt = 0; kt < NKT; ++kt) {
        if (kt + 1 < NKT) {
            aN = *(const float4*)(Ap + (kt + 1) * 8);
            bN = *(const float4*)(Bp + (size_t)(kt + 1) * 8 * DD);
        }
#pragma unroll
        for (int kk = 0; kk < 8; ++kk) {
            float4 a0 = *(const float4*)&As[buf][kk][ty << 2];
            float4 a1 = *(const float4*)&As[buf][kk][64 + (ty << 2)];
            float4 b0 = *(const float4*)&Bs[buf][kk][tx << 2];
            float4 b1 = *(const float4*)&Bs[buf][kk][64 + (tx << 2)];
            float a[8] = {a0.x, a0.y, a0.z, a0.w, a1.x, a1.y, a1.z, a1.w};
            float b[8] = {b0.x, b0.y, b0.z, b0.w, b1.x, b1.y, b1.z, b1.w};
#pragma unroll
            for (int i = 0; i < 8; ++i)
#pragma unroll
                for (int j = 0; j < 8; ++j)
                    acc[i][j] += a[i] * b[j];
        }
        if (kt + 1 < NKT) {
            int nb = buf ^ 1;
            As[nb][ak + 0][ar] = aN.x;
            As[nb][ak + 1][ar] = aN.y;
            As[nb][ak + 2][ar] = aN.z;
            As[nb][ak + 3][ar] = aN.w;
            *(float4*)&Bs[nb][br][bc] = bN;
            __syncthreads();
            buf = nb;
        }
    }

    const int col0 = bn + (tx << 2);
    const int col1 = col0 + 64;
    float4 bi0 = *(const float4*)&bias[col0];
    float4 bi1 = *(const float4*)&bias[col1];
#pragma unroll
    for (int g = 0; g < 2; ++g) {
#pragma unroll
        for (int r = 0; r < 4; ++r) {
            int row = bm + (ty << 2) + g * 64 + r;
            if (row < NN) {
                float s = g_idi[row];
                int ia = g * 4 + r;
                float4 o0, o1;
                o0.x = acc[ia][0] * s + bi0.x;
                o0.y = acc[ia][1] * s + bi0.y;
                o0.z = acc[ia][2] * s + bi0.z;
                o0.w = acc[ia][3] * s + bi0.w;
                o1.x = acc[ia][4] * s + bi1.x;
                o1.y = acc[ia][5] * s + bi1.y;
                o1.z = acc[ia][6] * s + bi1.z;
                o1.w = acc[ia][7] * s + bi1.w;
                if (DO_ELU) {
                    o0.x = o0.x > 0.f ? o0.x : expm1f(o0.x);
                    o0.y = o0.y > 0.f ? o0.y : expm1f(o0.y);
                    o0.z = o0.z > 0.f ? o0.z : expm1f(o0.z);
                    o0.w = o0.w > 0.f ? o0.w : expm1f(o0.w);
                    o1.x = o1.x > 0.f ? o1.x : expm1f(o1.x);
                    o1.y = o1.y > 0.f ? o1.y : expm1f(o1.y);
                    o1.z = o1.z > 0.f ? o1.z : expm1f(o1.z);
                    o1.w = o1.w > 0.f ? o1.w : expm1f(o1.w);
                }
                *(float4*)&C[(size_t)row * DD + col0] = o0;
                *(float4*)&C[(size_t)row * DD + col1] = o1;
            }
        }
    }
}

// ---------------- launch ----------------------------------------------------
extern "C" void kernel_launch(void* const* d_in, const int* in_sizes, int n_in,
                              void* d_out, int out_size) {
    (void)in_sizes; (void)n_in; (void)out_size;
    const float* h   = (const float*)d_in[0];
    const int*   src = (const int*)  d_in[1];
    const int*   dst = (const int*)  d_in[2];
    const float* ew  = (const float*)d_in[3];
    const float* W0  = (const float*)d_in[4];
    const float* b0  = (const float*)d_in[5];
    const float* W1  = (const float*)d_in[6];
    const float* b1  = (const float*)d_in[7];
    const float* W2  = (const float*)d_in[8];
    const float* b2  = (const float*)d_in[9];
    float* out = (float*)d_out;

    const int TB = 256;
    dim3 gemm_grid(MPAD / 128, DD / 128);                // 79 x 4
    const int drop_blocks = (ND / 4 + TB - 1) / TB;      // 5000

    // CSR build (recomputed each call: deterministic modulo fp-benign fill order)
    k_zero_deg<<<(NN + TB - 1) / TB, TB>>>();
    k_count_deg<<<(EE + TB - 1) / TB, TB>>>(src, dst);
    k_inv_deg<<<(NN + TB - 1) / TB, TB>>>();
    k_scan<<<1, 1024>>>();
    k_fill<<<(EE + TB - 1) / TB, TB>>>(src, dst, ew);

    // layer 0
    k_dropout_scale<<<drop_blocks, TB>>>(h, DK0.a, DK0.b);
    k_aggregate<<<NN, 128>>>();
    k_gemm<true><<<gemm_grid, TB>>>(W0, b0, nullptr);

    // layer 1
    k_dropout_scale<<<drop_blocks, TB>>>(nullptr, DK1.a, DK1.b);
    k_aggregate<<<NN, 128>>>();
    k_gemm<true><<<gemm_grid, TB>>>(W1, b1, nullptr);

    // layer 2 (no activation, write to d_out)
    k_dropout_scale<<<drop_blocks, TB>>>(nullptr, DK2.a, DK2.b);
    k_aggregate<<<NN, 128>>>();
    k_gemm<false><<<gemm_grid, TB>>>(W2, b2, out);
}

// round 9
// speedup vs baseline: 1.7943x; 1.4689x over previous
#include <cuda_runtime.h>
#include <cuda_bf16.h>
#include <math.h>
#include <stdint.h>

typedef unsigned int u32;
typedef unsigned long long u64;

#define NN 10000
#define NPAD2 10240           /* padded degree array for int2 scan loads */
#define EE 160000
#define DD 512
#define ND (NN * DD)          /* 5,120,000 */
#define MPAD 10112            /* 79 * 128 */

// ---------------- scratch (static device globals: allocation-free) ----------
__device__ __align__(16) float g_xs[ND];                 // dropout'd + src-normalized
__device__ __align__(16) float g_tmp[ND];                // layer output (fp32)
__device__ __align__(16) __nv_bfloat16 g_ahi[MPAD * DD]; // agg split hi (padded rows stay 0)
__device__ __align__(16) __nv_bfloat16 g_alo[MPAD * DD]; // agg split lo
__device__ __align__(16) __nv_bfloat16 g_wthi[3 * DD * DD]; // W^T split hi, per layer
__device__ __align__(16) __nv_bfloat16 g_wtlo[3 * DD * DD]; // W^T split lo
__device__ float g_ido[NN];
__device__ float g_idi[NN];
__device__ int   g_dego[NN];
__device__ __align__(16) int g_degi[NPAD2];
__device__ int   g_roff[NN + 1];
__device__ int   g_cur[NN];
__device__ int   g_esrc[EE];
__device__ float g_eew[EE];

// ---------------- JAX-compatible threefry2x32 (partitionable) ---------------
struct U2 { u32 a, b; };
constexpr u32 rotl_c(u32 v, int r) { return (v << r) | (v >> (32 - r)); }
constexpr U2 tf_host(u32 k0, u32 k1, u32 x0, u32 x1) {
    u32 ks2 = 0x1BD11BDAu ^ k0 ^ k1;
    x0 += k0; x1 += k1;
    const int R0[4] = {13, 15, 26, 6};
    const int R1[4] = {17, 29, 16, 24};
    for (int g = 0; g < 5; ++g) {
        for (int i = 0; i < 4; ++i) {
            int r = (g & 1) ? R1[i] : R0[i];
            x0 += x1; x1 = rotl_c(x1, r); x1 ^= x0;
        }
        switch (g) {
            case 0: x0 += k1;  x1 += ks2 + 1u; break;
            case 1: x0 += ks2; x1 += k0  + 2u; break;
            case 2: x0 += k0;  x1 += k1  + 3u; break;
            case 3: x0 += k1;  x1 += ks2 + 4u; break;
            default: x0 += ks2; x1 += k0 + 5u; break;
        }
    }
    return U2{x0, x1};
}
constexpr U2 DK0 = tf_host(0u, 42u, 0u, 0u);
constexpr U2 DK1 = tf_host(0u, 42u, 0u, 1u);
constexpr U2 DK2 = tf_host(0u, 42u, 0u, 2u);

__device__ __forceinline__ void tf_dev(u32 k0, u32 k1, u32& x0, u32& x1) {
    u32 ks2 = 0x1BD11BDAu ^ k0 ^ k1;
    x0 += k0; x1 += k1;
#define TFR(r) { x0 += x1; x1 = (x1 << (r)) | (x1 >> (32 - (r))); x1 ^= x0; }
    TFR(13) TFR(15) TFR(26) TFR(6)   x0 += k1;  x1 += ks2 + 1u;
    TFR(17) TFR(29) TFR(16) TFR(24)  x0 += ks2; x1 += k0  + 2u;
    TFR(13) TFR(15) TFR(26) TFR(6)   x0 += k0;  x1 += k1  + 3u;
    TFR(17) TFR(29) TFR(16) TFR(24)  x0 += k1;  x1 += ks2 + 4u;
    TFR(13) TFR(15) TFR(26) TFR(6)   x0 += ks2; x1 += k0  + 5u;
#undef TFR
}

// ---------------- mma.sync helpers (family-compatible, no 'a' features) -----
__device__ __forceinline__ u32 smem_u32(const void* p) {
    u32 a;
    asm("{ .reg .u64 t; cvta.to.shared.u64 t, %1; cvt.u32.u64 %0, t; }" : "=r"(a) : "l"(p));
    return a;
}
__device__ __forceinline__ void ldsm4(u32& r0, u32& r1, u32& r2, u32& r3, u32 addr) {
    asm volatile("ldmatrix.sync.aligned.m8n8.x4.shared.b16 {%0,%1,%2,%3}, [%4];"
                 : "=r"(r0), "=r"(r1), "=r"(r2), "=r"(r3) : "r"(addr));
}
__device__ __forceinline__ void mma_bf16(float& c0, float& c1, float& c2, float& c3,
                                         u32 a0, u32 a1, u32 a2, u32 a3,
                                         u32 b0, u32 b1) {
    asm volatile(
        "mma.sync.aligned.m16n8k16.row.col.f32.bf16.bf16.f32 "
        "{%0,%1,%2,%3}, {%4,%5,%6,%7}, {%8,%9}, {%0,%1,%2,%3};"
        : "+f"(c0), "+f"(c1), "+f"(c2), "+f"(c3)
        : "r"(a0), "r"(a1), "r"(a2), "r"(a3), "r"(b0), "r"(b1));
}

// ---------------- degree + CSR build ---------------------------------------
__global__ void k_zero_deg() {
    int i = blockIdx.x * blockDim.x + threadIdx.x;
    if (i < NN) g_dego[i] = 0;
    if (i < NPAD2) g_degi[i] = 0;
}

__global__ void k_count_deg(const int* __restrict__ src, const int* __restrict__ dst) {
    int e = blockIdx.x * blockDim.x + threadIdx.x;
    if (e < EE) {
        atomicAdd(&g_dego[src[e]], 1);
        atomicAdd(&g_degi[dst[e]], 1);
    }
}

// fused: inverse-sqrt degrees + exclusive scan of degi -> roff/cur. 1024 threads.
__global__ void k_scan() {
    const int t = threadIdx.x;
    for (int i = t; i < NN; i += 1024) {
        g_ido[i] = rsqrtf(fmaxf((float)g_dego[i], 1.0f));
        g_idi[i] = rsqrtf(fmaxf((float)g_degi[i], 1.0f));
    }
    const int2* p = (const int2*)g_degi + t * 5;
    int2 d0 = p[0], d1 = p[1], d2 = p[2], d3 = p[3], d4 = p[4];
    int vals[10] = {d0.x, d0.y, d1.x, d1.y, d2.x, d2.y, d3.x, d3.y, d4.x, d4.y};
    int loc[10], sum = 0;
#pragma unroll
    for (int i = 0; i < 10; ++i) { loc[i] = sum; sum += vals[i]; }
    int lane = t & 31, w = t >> 5;
    int inc = sum;
#pragma unroll
    for (int o = 1; o < 32; o <<= 1) {
        int x = __shfl_up_sync(0xFFFFFFFFu, inc, o);
        if (lane >= o) inc += x;
    }
    __shared__ int ws[32];
    if (lane == 31) ws[w] = inc;
    __syncthreads();
    if (w == 0) {
        int x = ws[lane];
#pragma unroll
        for (int o = 1; o < 32; o <<= 1) {
            int y = __shfl_up_sync(0xFFFFFFFFu, x, o);
            if (lane >= o) x += y;
        }
        ws[lane] = x;
    }
    __syncthreads();
    int excl = inc - sum + (w ? ws[w - 1] : 0);
#pragma unroll
    for (int i = 0; i < 10; ++i) {
        int idx = t * 10 + i;
        if (idx < NN) { int o = excl + loc[i]; g_roff[idx] = o; g_cur[idx] = o; }
    }
    if (t == 0) g_roff[NN] = ws[31];
}

__global__ void k_fill(const int* __restrict__ src, const int* __restrict__ dst,
                       const float* __restrict__ ew) {
    int e = blockIdx.x * blockDim.x + threadIdx.x;
    if (e < EE) {
        int pos = atomicAdd(&g_cur[dst[e]], 1);
        g_esrc[pos] = src[e];
        g_eew[pos] = ew[e];
    }
}

// ---------------- weight transpose + bf16 split -----------------------------
// Wt[n][k] = W[k][n]; hi = bf16(v), lo = bf16(v - hi). All 3 layers in one launch.
__global__ void k_wsplit(const float* __restrict__ W0, const float* __restrict__ W1,
                         const float* __restrict__ W2) {
    __shared__ float tile[32][33];
    const int L = blockIdx.z;
    const float* __restrict__ W = (L == 0) ? W0 : ((L == 1) ? W1 : W2);
    __nv_bfloat16* __restrict__ TH = g_wthi + (size_t)L * DD * DD;
    __nv_bfloat16* __restrict__ TL = g_wtlo + (size_t)L * DD * DD;
    const int bx = blockIdx.x * 32, by = blockIdx.y * 32;
    const int tx = threadIdx.x, ty = threadIdx.y;
#pragma unroll
    for (int i = 0; i < 32; i += 8)
        tile[ty + i][tx] = W[(size_t)(by + ty + i) * DD + bx + tx];
    __syncthreads();
#pragma unroll
    for (int i = 0; i < 32; i += 8) {
        float v = tile[tx][ty + i];
        __nv_bfloat16 h = __float2bfloat16(v);
        float lo = v - __bfloat162float(h);
        TH[(size_t)(bx + ty + i) * DD + by + tx] = h;
        TL[(size_t)(bx + ty + i) * DD + by + tx] = __float2bfloat16(lo);
    }
}

// ---------------- fused dropout + src-degree normalization ------------------
__global__ void k_dropout_scale(const float* __restrict__ xin_arg, u32 k0, u32 k1) {
    const float* __restrict__ xin = xin_arg ? xin_arg : (const float*)g_tmp;
    int q = blockIdx.x * blockDim.x + threadIdx.x;
    if (q >= ND / 4) return;
    int j0 = q << 2;
    float4 v = *(const float4*)(xin + j0);
    float s = g_ido[j0 >> 9] * 1.25f;
    float vv[4] = {v.x, v.y, v.z, v.w};
    float o[4];
#pragma unroll
    for (int t = 0; t < 4; ++t) {
        u32 x0 = 0u, x1 = (u32)(j0 + t);
        tf_dev(k0, k1, x0, x1);
        u32 bits = x0 ^ x1;
        float u = __uint_as_float((bits >> 9) | 0x3f800000u) - 1.0f;
        o[t] = (u < 0.8f) ? vv[t] * s : 0.0f;
    }
    *(float4*)(g_xs + j0) = make_float4(o[0], o[1], o[2], o[3]);
}

// ---------------- CSR aggregation -> bf16 hi/lo split -----------------------
__global__ __launch_bounds__(128)
void k_aggregate() {
    const int n = blockIdx.x;
    const int c = threadIdx.x << 2;
    const int beg = g_roff[n];
    const int end = g_roff[n + 1];
    float4 acc = make_float4(0.f, 0.f, 0.f, 0.f);
    int i = beg;
    for (; i + 1 < end; i += 2) {
        int s0 = g_esrc[i],  s1 = g_esrc[i + 1];
        float w0 = g_eew[i], w1 = g_eew[i + 1];
        float4 v0 = *(const float4*)(g_xs + (size_t)s0 * DD + c);
        float4 v1 = *(const float4*)(g_xs + (size_t)s1 * DD + c);
        acc.x += v0.x * w0 + v1.x * w1;
        acc.y += v0.y * w0 + v1.y * w1;
        acc.z += v0.z * w0 + v1.z * w1;
        acc.w += v0.w * w0 + v1.w * w1;
    }
    if (i < end) {
        int s0 = g_esrc[i];
        float w0 = g_eew[i];
        float4 v0 = *(const float4*)(g_xs + (size_t)s0 * DD + c);
        acc.x += v0.x * w0; acc.y += v0.y * w0;
        acc.z += v0.z * w0; acc.w += v0.w * w0;
    }
    float a[4] = {acc.x, acc.y, acc.z, acc.w};
    __nv_bfloat162 h01, h23, l01, l23;
    __nv_bfloat16 h0 = __float2bfloat16(a[0]);
    __nv_bfloat16 h1 = __float2bfloat16(a[1]);
    __nv_bfloat16 h2 = __float2bfloat16(a[2]);
    __nv_bfloat16 h3 = __float2bfloat16(a[3]);
    h01.x = h0; h01.y = h1; h23.x = h2; h23.y = h3;
    l01.x = __float2bfloat16(a[0] - __bfloat162float(h0));
    l01.y = __float2bfloat16(a[1] - __bfloat162float(h1));
    l23.x = __float2bfloat16(a[2] - __bfloat162float(h2));
    l23.y = __float2bfloat16(a[3] - __bfloat162float(h3));
    uint2 uh, ul;
    uh.x = *(u32*)&h01; uh.y = *(u32*)&h23;
    ul.x = *(u32*)&l01; ul.y = *(u32*)&l23;
    *(uint2*)(g_ahi + (size_t)n * DD + c) = uh;
    *(uint2*)(g_alo + (size_t)n * DD + c) = ul;
}

// ---------------- HMMA bf16x3 GEMM ------------------------------------------
// C[M,512] = (Ahi+Alo) @ (Wthi+Wtlo)^T via mma.sync m16n8k16 bf16, fp32 accum.
// CTA tile 128x128, 8 warps (2x4), warp tile 64x32, K chunks of 16, dbl-buffer.
#define SAST 24    /* smem row stride in bf16 (16 + 8 pad) */

template<bool DO_ELU>
__global__ __launch_bounds__(256, 2)
void k_gemm_mma(int layer, const float* __restrict__ bias, float* __restrict__ Carg) {
    float* __restrict__ C = Carg ? Carg : (float*)g_tmp;
    __shared__ __nv_bfloat16 sA[2][2][128][SAST];   // [buf][hi/lo][row][k]
    __shared__ __nv_bfloat16 sB[2][2][128][SAST];

    const int t = threadIdx.x;
    const int lane = t & 31;
    const int wid = t >> 5;
    const int wm = wid >> 2;        // 0..1
    const int wn = wid & 3;         // 0..3
    const int g = lane >> 2, tg = lane & 3;
    const int bm = blockIdx.x * 128;
    const int bn = blockIdx.y * 128;

    // global load assignment: row r (0..127), half (0/1) -> 8 bf16 = uint4
    const int r = t >> 1, half = t & 1;
    const uint4* GA_hi = (const uint4*)g_ahi + (size_t)(bm + r) * 64 + half;
    const uint4* GA_lo = (const uint4*)g_alo + (size_t)(bm + r) * 64 + half;
    const uint4* GB_hi = (const uint4*)(g_wthi + (size_t)layer * DD * DD)
                         + (size_t)(bn + r) * 64 + half;
    const uint4* GB_lo = (const uint4*)(g_wtlo + (size_t)layer * DD * DD)
                         + (size_t)(bn + r) * 64 + half;

    float acc[4][4][4];
#pragma unroll
    for (int i = 0; i < 4; ++i)
#pragma unroll
        for (int j = 0; j < 4; ++j)
#pragma unroll
            for (int q = 0; q < 4; ++q) acc[i][j][q] = 0.0f;

    // preload chunk 0
    {
        uint4 va = GA_hi[0], vb = GA_lo[0], vc = GB_hi[0], vd = GB_lo[0];
        *(uint4*)&sA[0][0][r][half * 8] = va;
        *(uint4*)&sA[0][1][r][half * 8] = vb;
        *(uint4*)&sB[0][0][r][half * 8] = vc;
        *(uint4*)&sB[0][1][r][half * 8] = vd;
    }
    __syncthreads();

    const int NCH = DD / 16;   // 32
    int buf = 0;
    for (int ch = 0; ch < NCH; ++ch) {
        uint4 va, vb, vc, vd;
        const bool more = (ch + 1 < NCH);
        if (more) {
            va = GA_hi[(ch + 1) * 2];
            vb = GA_lo[(ch + 1) * 2];
            vc = GB_hi[(ch + 1) * 2];
            vd = GB_lo[(ch + 1) * 2];
        }

        // B fragments for this warp (4 n-tiles, hi+lo)
        u32 bh0[4], bh1[4], bl0[4], bl1[4];
#pragma unroll
        for (int nt = 0; nt < 4; ++nt) {
            const int n = wn * 32 + nt * 8 + g;
            const __nv_bfloat16* ph = &sB[buf][0][n][2 * tg];
            const __nv_bfloat16* pl = &sB[buf][1][n][2 * tg];
            bh0[nt] = *(const u32*)ph;
            bh1[nt] = *(const u32*)(ph + 8);
            bl0[nt] = *(const u32*)pl;
            bl1[nt] = *(const u32*)(pl + 8);
        }
#pragma unroll
        for (int mt = 0; mt < 4; ++mt) {
            const int arow = wm * 64 + mt * 16 + (lane & 15);
            const int acol = (lane >> 4) * 8;
            u32 ah0, ah1, ah2, ah3, al0, al1, al2, al3;
            ldsm4(ah0, ah1, ah2, ah3, smem_u32(&sA[buf][0][arow][acol]));
            ldsm4(al0, al1, al2, al3, smem_u32(&sA[buf][1][arow][acol]));
#pragma unroll
            for (int nt = 0; nt < 4; ++nt) {
                mma_bf16(acc[mt][nt][0], acc[mt][nt][1], acc[mt][nt][2], acc[mt][nt][3],
                         ah0, ah1, ah2, ah3, bh0[nt], bh1[nt]);
                mma_bf16(acc[mt][nt][0], acc[mt][nt][1], acc[mt][nt][2], acc[mt][nt][3],
                         ah0, ah1, ah2, ah3, bl0[nt], bl1[nt]);
                mma_bf16(acc[mt][nt][0], acc[mt][nt][1], acc[mt][nt][2], acc[mt][nt][3],
                         al0, al1, al2, al3, bh0[nt], bh1[nt]);
            }
        }

        if (more) {
            const int nb = buf ^ 1;
            *(uint4*)&sA[nb][0][r][half * 8] = va;
            *(uint4*)&sA[nb][1][r][half * 8] = vb;
            *(uint4*)&sB[nb][0][r][half * 8] = vc;
            *(uint4*)&sB[nb][1][r][half * 8] = vd;
            __syncthreads();
            buf = nb;
        }
    }

    // epilogue: scale by deg_in^-0.5, add bias, optional ELU
#pragma unroll
    for (int mt = 0; mt < 4; ++mt) {
#pragma unroll
        for (int half_m = 0; half_m < 2; ++half_m) {
            const int row = bm + wm * 64 + mt * 16 + g + half_m * 8;
            if (row < NN) {
                const float s = g_idi[row];
#pragma unroll
                for (int nt = 0; nt < 4; ++nt) {
                    const int col = bn + wn * 32 + nt * 8 + 2 * tg;
                    float2 bv = *(const float2*)&bias[col];
                    float c0 = acc[mt][nt][half_m * 2 + 0] * s + bv.x;
                    float c1 = acc[mt][nt][half_m * 2 + 1] * s + bv.y;
                    if (DO_ELU) {
                        c0 = c0 > 0.f ? c0 : expm1f(c0);
                        c1 = c1 > 0.f ? c1 : expm1f(c1);
                    }
                    *(float2*)&C[(size_t)row * DD + col] = make_float2(c0, c1);
                }
            }
        }
    }
}

// ---------------- launch ----------------------------------------------------
extern "C" void kernel_launch(void* const* d_in, const int* in_sizes, int n_in,
                              void* d_out, int out_size) {
    (void)in_sizes; (void)n_in; (void)out_size;
    const float* h   = (const float*)d_in[0];
    const int*   src = (const int*)  d_in[1];
    const int*   dst = (const int*)  d_in[2];
    const float* ew  = (const float*)d_in[3];
    const float* W0  = (const float*)d_in[4];
    const float* b0  = (const float*)d_in[5];
    const float* W1  = (const float*)d_in[6];
    const float* b1  = (const float*)d_in[7];
    const float* W2  = (const float*)d_in[8];
    const float* b2  = (const float*)d_in[9];
    float* out = (float*)d_out;

    const int TB = 256;
    dim3 gemm_grid(MPAD / 128, DD / 128);            // 79 x 4
    const int drop_blocks = (ND / 4 + TB - 1) / TB;  // 5000

    // CSR build + weight prep
    k_zero_deg<<<(NPAD2 + TB - 1) / TB, TB>>>();
    k_count_deg<<<(EE + TB - 1) / TB, TB>>>(src, dst);
    k_scan<<<1, 1024>>>();
    k_fill<<<(EE + TB - 1) / TB, TB>>>(src, dst, ew);
    k_wsplit<<<dim3(16, 16, 3), dim3(32, 8)>>>(W0, W1, W2);

    // layer 0
    k_dropout_scale<<<drop_blocks, TB>>>(h, DK0.a, DK0.b);
    k_aggregate<<<NN, 128>>>();
    k_gemm_mma<true><<<gemm_grid, TB>>>(0, b0, nullptr);

    // layer 1
    k_dropout_scale<<<drop_blocks, TB>>>(nullptr, DK1.a, DK1.b);
    k_aggregate<<<NN, 128>>>();
    k_gemm_mma<true><<<gemm_grid, TB>>>(1, b1, nullptr);

    // layer 2 (no activation, write to d_out)
    k_dropout_scale<<<drop_blocks, TB>>>(nullptr, DK2.a, DK2.b);
    k_aggregate<<<NN, 128>>>();
    k_gemm_mma<false><<<gemm_grid, TB>>>(2, b2, out);
}